// round 4
// baseline (speedup 1.0000x reference)
#include <cuda_runtime.h>

#define NQ     18
#define NREPS  3
#define NBATCH 64
#define IDIM   32

__device__ __forceinline__ float2 cmul(float2 a, float2 b) {
    return make_float2(a.x * b.x - a.y * b.y, a.x * b.y + a.y * b.x);
}
__device__ __forceinline__ float2 cmulc(float2 a, float2 b) {   // a * conj(b)
    return make_float2(a.x * b.x + a.y * b.y, a.y * b.x - a.x * b.y);
}
__device__ __forceinline__ float2 cadd(float2 a, float2 b) {
    return make_float2(a.x + b.x, a.y + b.y);
}
__device__ __forceinline__ float2 csub(float2 a, float2 b) {
    return make_float2(a.x - b.x, a.y - b.y);
}

// One block per batch element. Exact bond-8 transfer-matrix contraction with
// PAIR-FUSED superoperators: M_q = G_t[z1] G_{t+1}[z2]  (q = 2*z1 + z2).
//   rho^(t+2) = sum_q M^T rho M*     D[t+1] = sum_q (-1)^{z2} M^T rho M*
//   sig^(t)   = sum_q M sig M^dag    S[t]   = sum_q (-1)^{z1} M sig M^dag
//   <Z_t> = Re(rho^(t) . S[t]) (t even) | Re(D[t] . sig^(t+1)) (t odd)
// -> only 9 sequential steps per sweep direction, run concurrently by the
// two 128-thread halves of the block.
__global__ __launch_bounds__(256, 1) void qenc_kernel(
    const float* __restrict__ xin,   // (64, 32)
    const float* __restrict__ vp,    // (3, 18, 2)
    float* __restrict__ out)         // (64, 18)
{
    const int b   = blockIdx.x;
    const int tid = threadIdx.x;

    // raw region: first holds G[18][2][8][9] (20736 B); after M is built it is
    // reused for the four 9x8x8 history arrays (18432 B).
    __shared__ __align__(16) char raw[NQ * 2 * 8 * 9 * sizeof(float2)];
    __shared__ float2 M[9][4][8][9];      // pair superop factors (padded)
    __shared__ float2 tmpL[4][8][9];
    __shared__ float2 tmpR[4][8][9];
    __shared__ float  sc[NQ][5][2];       // (cos,sin) of: A1, A2B1, A3B2, B3, x
    __shared__ float  zred[NQ][8];

    typedef float2 (*Gptr)[2][8][9];
    typedef float2 (*Hptr)[8][8];
    Gptr G    = reinterpret_cast<Gptr>(raw);
    Hptr rhoH = reinterpret_cast<Hptr>(raw);                    // rho^(0,2,..,16)
    Hptr sigH = reinterpret_cast<Hptr>(raw + 4608);             // sig^(18,16,..,2)
    Hptr Dh   = reinterpret_cast<Hptr>(raw + 9216);             // D[1,3,..,17]
    Hptr SH   = reinterpret_cast<Hptr>(raw + 13824);            // S[16,14,..,0]

    // ---- setup: 5 sincos per site (RY(a)RY(b)=RY(a+b) collapses products) --
    if (tid < NQ * 5) {
        const int k = tid / 5;
        const int g = tid - k * 5;
        float th;
        if (g == 0)      th = vp[(0 * NQ + k) * 2 + 0];
        else if (g == 1) th = vp[(1 * NQ + k) * 2 + 0] + vp[(0 * NQ + k) * 2 + 1];
        else if (g == 2) th = vp[(2 * NQ + k) * 2 + 0] + vp[(1 * NQ + k) * 2 + 1];
        else if (g == 3) th = vp[(2 * NQ + k) * 2 + 1];
        else             th = xin[b * IDIM + k];
        float s, c;
        __sincosf(0.5f * th, &s, &c);
        sc[k][g][0] = c;
        sc[k][g][1] = s;
    }
    __syncthreads();

    // ---- build G[k][z][p][n] (2304 entries, 9/thread) ----------------------
    #pragma unroll
    for (int ii = 0; ii < 9; ++ii) {
        const int idx = tid + ii * 256;
        const int k = idx >> 7;
        const int z = (idx >> 6) & 1;
        const int p = (idx >> 3) & 7;
        const int n = idx & 7;
        const int n1 = n & 1, n2 = (n >> 1) & 1, n3 = (n >> 2) & 1;
        const int p1 = p & 1, p2 = (p >> 1) & 1, p3 = (p >> 2) & 1;
        const float r3  = (z == n3) ? sc[k][3][0] : (z == 0 ? -sc[k][3][1] : sc[k][3][1]);
        const int   i3  = n3 ^ p3;
        const float rc3 = (i3 == n2) ? sc[k][2][0] : (i3 == 0 ? -sc[k][2][1] : sc[k][2][1]);
        const int   i2  = n2 ^ p2;
        const float rc2 = (i2 == n1) ? sc[k][1][0] : (i2 == 0 ? -sc[k][1][1] : sc[k][1][1]);
        const float coef = r3 * rc3 * rc2;
        const float c1 = sc[k][0][0], s1 = sc[k][0][1];
        const float cx = sc[k][4][0], sx = sc[k][4][1];
        float2 w;
        if ((n1 ^ p1) == 0) w = make_float2(c1 * cx,  s1 * sx);
        else                w = make_float2(s1 * cx, -c1 * sx);
        G[k][z][p][n] = make_float2(coef * w.x, coef * w.y);
    }
    __syncthreads();

    // ---- build M[pr][q][p][n] = sum_m G[2pr][z1][p][m] * G[2pr+1][z2][m][n] --
    #pragma unroll
    for (int ii = 0; ii < 9; ++ii) {
        const int idx = tid + ii * 256;
        const int pr = idx >> 8;
        const int q  = (idx >> 6) & 3;
        const int p  = (idx >> 3) & 7;
        const int n  = idx & 7;
        const int z1 = q >> 1, z2 = q & 1;
        float2 acc = make_float2(0.f, 0.f);
        #pragma unroll
        for (int m = 0; m < 8; ++m)
            acc = cadd(acc, cmul(G[2 * pr][z1][p][m], G[2 * pr + 1][z2][m][n]));
        M[pr][q][p][n] = acc;
    }
    __syncthreads();   // G is dead; raw becomes the history region

    // ---- boundary envs ------------------------------------------------------
    if (tid < 64) {
        rhoH[0][tid >> 3][tid & 7] = make_float2(tid == 0 ? 1.f : 0.f, 0.f);
    } else if (tid < 128) {
        const int j = tid - 64;
        sigH[0][j >> 3][j & 7] = make_float2(1.f, 0.f);
    }
    __syncthreads();

    // ---- 9-step pair sweeps: warps 0-3 left, warps 4-7 right ---------------
    const int half = tid >> 7;
    const int w4   = (tid >> 5) & 3;
    const int lane = tid & 31;
    const int qh   = lane >> 4;         // q-half selector
    const int il   = (lane >> 3) & 1;
    const int a    = lane & 7;          // stage1 col / stage2 output col j
    const int i    = w4 * 2 + il;       // owned row

    for (int s = 0; s < 9; ++s) {
        if (half == 0) {
            // left step s: consumes rhoH[s] (rho^(2s)), pair pr = s
            const float2* rr = &rhoH[s][0][0];
            #pragma unroll
            for (int qq = 0; qq < 2; ++qq) {
                const int q = qh + 2 * qq;
                const float2* Mq = &M[s][q][0][0];
                float2 acc0 = make_float2(0.f, 0.f);
                float2 acc1 = make_float2(0.f, 0.f);
                #pragma unroll
                for (int m = 0; m < 8; m += 2) {
                    acc0 = cadd(acc0, cmul(Mq[m * 9 + i],       rr[m * 8 + a]));
                    acc1 = cadd(acc1, cmul(Mq[(m + 1) * 9 + i], rr[(m + 1) * 8 + a]));
                }
                tmpL[q][i][a] = cadd(acc0, acc1);
            }
            __syncwarp();
            // stage2: terms for q = 2*qh, 2*qh+1
            float2 t0 = make_float2(0.f, 0.f);
            float2 t1 = make_float2(0.f, 0.f);
            {
                const int q0 = 2 * qh, q1 = 2 * qh + 1;
                const float2* Mq0 = &M[s][q0][0][0];
                const float2* Mq1 = &M[s][q1][0][0];
                #pragma unroll
                for (int a2 = 0; a2 < 8; ++a2) {
                    t0 = cadd(t0, cmulc(tmpL[q0][i][a2], Mq0[a2 * 9 + a]));
                    t1 = cadd(t1, cmulc(tmpL[q1][i][a2], Mq1[a2 * 9 + a]));
                }
            }
            float2 pp = cadd(t0, t1);           // plain sum over my two q's
            float2 pd = csub(t0, t1);           // (-1)^{z2} signed
            float2 ppo, pdo;
            ppo.x = __shfl_xor_sync(0xffffffffu, pp.x, 16);
            ppo.y = __shfl_xor_sync(0xffffffffu, pp.y, 16);
            pdo.x = __shfl_xor_sync(0xffffffffu, pd.x, 16);
            pdo.y = __shfl_xor_sync(0xffffffffu, pd.y, 16);
            if (qh == 0) {
                if (s < 8) rhoH[s + 1][i][a] = cadd(pp, ppo);
            } else {
                Dh[s][i][a] = cadd(pd, pdo);    // D[2s+1]
            }
        } else {
            // right step s: consumes sigH[s] (sig^(18-2s)), pair pr = 8 - s
            const int pr = 8 - s;
            const float2* ss = &sigH[s][0][0];
            #pragma unroll
            for (int qq = 0; qq < 2; ++qq) {
                const int q = qh + 2 * qq;
                const float2* Mq = &M[pr][q][0][0];
                float2 acc0 = make_float2(0.f, 0.f);
                float2 acc1 = make_float2(0.f, 0.f);
                #pragma unroll
                for (int m = 0; m < 8; m += 2) {
                    acc0 = cadd(acc0, cmul(Mq[i * 9 + m],     ss[m * 8 + a]));
                    acc1 = cadd(acc1, cmul(Mq[i * 9 + m + 1], ss[(m + 1) * 8 + a]));
                }
                tmpR[q][i][a] = cadd(acc0, acc1);
            }
            __syncwarp();
            float2 t0 = make_float2(0.f, 0.f);
            float2 t1 = make_float2(0.f, 0.f);
            {
                const int q0 = 2 * qh, q1 = 2 * qh + 1;
                const float2* Mq0 = &M[pr][q0][0][0];
                const float2* Mq1 = &M[pr][q1][0][0];
                #pragma unroll
                for (int a2 = 0; a2 < 8; ++a2) {
                    t0 = cadd(t0, cmulc(tmpR[q0][i][a2], Mq0[a * 9 + a2]));
                    t1 = cadd(t1, cmulc(tmpR[q1][i][a2], Mq1[a * 9 + a2]));
                }
            }
            float2 pp = cadd(t0, t1);           // my z1 partial (sign (-1)^qh)
            float2 ppo;
            ppo.x = __shfl_xor_sync(0xffffffffu, pp.x, 16);
            ppo.y = __shfl_xor_sync(0xffffffffu, pp.y, 16);
            if (qh == 0) {
                if (s < 8) sigH[s + 1][i][a] = cadd(pp, ppo);
            } else {
                SH[s][i][a] = csub(ppo, pp);    // S[16-2s] = (+z1=0) - (z1=1)
            }
        }
        __syncthreads();
    }

    // ---- observables --------------------------------------------------------
    // even t=2e: Re(rhoH[e] . SH[8-e]);  odd t=2e+1: Re(Dh[e] . sigH[8-e])
    if (tid < NQ * 8) {
        const int w = tid >> 3;
        const int r = tid & 7;
        const int e = w >> 1;
        const float2* dmat = (w & 1) ? &Dh[e][r][0]   : &rhoH[e][r][0];
        const float2* smat = (w & 1) ? &sigH[8 - e][r][0] : &SH[8 - e][r][0];
        float acc = 0.f;
        #pragma unroll
        for (int j = 0; j < 8; ++j)
            acc += dmat[j].x * smat[j].x - dmat[j].y * smat[j].y;
        zred[w][r] = acc;
    }
    __syncthreads();
    if (tid < NQ) {
        float sum = 0.f;
        #pragma unroll
        for (int j = 0; j < 8; ++j) sum += zred[tid][j];
        out[b * NQ + tid] = sum;
    }
}

extern "C" void kernel_launch(void* const* d_in, const int* in_sizes, int n_in,
                              void* d_out, int out_size)
{
    const float* x  = (const float*)d_in[0];   // input_vec (64,32)
    const float* vp = (const float*)d_in[1];   // var_params (3,18,2)
    if (n_in >= 2 && in_sizes[0] == NREPS * NQ * 2) {
        x  = (const float*)d_in[1];
        vp = (const float*)d_in[0];
    }
    qenc_kernel<<<NBATCH, 256>>>(x, vp, (float*)d_out);
}